// round 17
// baseline (speedup 1.0000x reference)
#include <cuda_runtime.h>
#include <cuda_bf16.h>
#include <mma.h>
#include <cstdint>

using namespace nvcuda;

#define NN 256
#define MATS (256LL * 256 * 256)

// scratch (static __device__ arrays: allocation-free)
__device__ __nv_bfloat16 g_Phi[MATS], g_Plo[MATS];
__device__ __nv_bfloat16 g_P2hi[MATS], g_P2lo[MATS];
__device__ float g_P3[MATS], g_P4[MATS];

__device__ __forceinline__ uint32_t smem_u32(const void* p) {
    uint32_t a;
    asm("{ .reg .u64 t; cvta.to.shared.u64 t, %1; cvt.u32.u64 %0, t; }" : "=r"(a) : "l"(p));
    return a;
}
__device__ __forceinline__ void cpa16(uint32_t dst, const void* src) {
    asm volatile("cp.async.cg.shared.global [%0], [%1], 16;" :: "r"(dst), "l"(src));
}
__device__ __forceinline__ void cpa_commit() {
    asm volatile("cp.async.commit_group;" ::: "memory");
}
__device__ __forceinline__ float bf2f(__nv_bfloat16 v) { return __bfloat162float(v); }

// ---------------------------------------------------------------------------
// prep: threshold + row-normalize. Warp per row. Writes bf16 hi/lo of P +
// slots 0/1.
// ---------------------------------------------------------------------------
__global__ void __launch_bounds__(256) prep_kernel(const float* __restrict__ A,
                                                   __nv_bfloat16* __restrict__ Phi,
                                                   __nv_bfloat16* __restrict__ Plo,
                                                   float* __restrict__ out)
{
    int row = blockIdx.x * 8 + (threadIdx.x >> 5);
    int lane = threadIdx.x & 31;
    int n = row & 255;

    const float* arow = A + (size_t)row * NN + lane * 8;
    float4 v0 = *(const float4*)(arow);
    float4 v1 = *(const float4*)(arow + 4);
    float f[8] = {v0.x, v0.y, v0.z, v0.w, v1.x, v1.y, v1.z, v1.w};
    float s = 0.0f;
    #pragma unroll
    for (int q = 0; q < 8; q++) {
        f[q] = (f[q] > 0.3f) ? f[q] : 0.0f;
        s += f[q];
    }
    #pragma unroll
    for (int o = 16; o; o >>= 1) s += __shfl_xor_sync(0xffffffffu, s, o);
    float dinv = (s > 0.0f) ? (1.0f / s) : 0.0f;

    uint32_t hp[4], lp[4];
    float p[8];
    #pragma unroll
    for (int q = 0; q < 4; q++) {
        p[2*q]   = f[2*q]   * dinv;
        p[2*q+1] = f[2*q+1] * dinv;
        __nv_bfloat16 h0 = __float2bfloat16_rn(p[2*q]);
        __nv_bfloat16 h1 = __float2bfloat16_rn(p[2*q+1]);
        __nv_bfloat162 hh; hh.x = h0; hh.y = h1;
        hp[q] = *(uint32_t*)&hh;
        __nv_bfloat162 ll;
        ll.x = __float2bfloat16_rn(p[2*q]   - bf2f(h0));
        ll.y = __float2bfloat16_rn(p[2*q+1] - bf2f(h1));
        lp[q] = *(uint32_t*)&ll;
    }
    size_t idx = (size_t)row * NN + lane * 8;
    *(uint4*)(Phi + idx) = make_uint4(hp[0], hp[1], hp[2], hp[3]);
    *(uint4*)(Plo + idx) = make_uint4(lp[0], lp[1], lp[2], lp[3]);

    if (lane == (n >> 3)) out[(size_t)row * 8 + 1] = p[n & 7];
    if (lane == 0)        out[(size_t)row * 8 + 0] = 1.0f;
}

// ---------------------------------------------------------------------------
// WMMA bf16-split GEMM (R8/R16 mainloop byte-exact): C = X * Y.
// CTA: 256 thr / 8 warps, tile 128x128, warp tile 64x32, K-chunk 32,
// THREE-stage cp.async pipeline (depth 2), sync top AND bottom of chunk.
// 3 split products: XhYh + XhYl + XlYh.
// Epilogue: smem-staged C + diag slot; then EITHER bf16 hi/lo split
// (Chi != null; P2 — consumed by later GEMM) OR plain fp32 (Cf != null;
// P3/P4 — consumed only by diag3, no split needed).
// blockIdx.z selects one of two problem descriptors (dual launch).
// ---------------------------------------------------------------------------
#define XLD 40
#define YLD 136
#define XARR_B (128 * XLD * 2)               // 10240
#define YARR_B (32 * YLD * 2)                // 8704
#define OFF_XL XARR_B
#define OFF_YH (2 * XARR_B)
#define OFF_YL (2 * XARR_B + YARR_B)
#define STAGE_B (2 * XARR_B + 2 * YARR_B)    // 37888
#define GEMM_SMEM (3 * STAGE_B)              // 113664 (2 CTA/SM)
#define CLD 132                              // epilogue stage ld; 128*132*4=67584 fits

__global__ void __launch_bounds__(256, 2)
gemm_wmma(const __nv_bfloat16* __restrict__ Xh0, const __nv_bfloat16* __restrict__ Xl0,
          const __nv_bfloat16* __restrict__ Yh0, const __nv_bfloat16* __restrict__ Yl0,
          __nv_bfloat16* __restrict__ Chi0, __nv_bfloat16* __restrict__ Clo0,
          float* __restrict__ Cf0, int slot0,
          const __nv_bfloat16* __restrict__ Xh1, const __nv_bfloat16* __restrict__ Xl1,
          const __nv_bfloat16* __restrict__ Yh1, const __nv_bfloat16* __restrict__ Yl1,
          __nv_bfloat16* __restrict__ Chi1, __nv_bfloat16* __restrict__ Clo1,
          float* __restrict__ Cf1, int slot1,
          float* __restrict__ out)
{
    const __nv_bfloat16* Xh = blockIdx.z ? Xh1 : Xh0;
    const __nv_bfloat16* Xl = blockIdx.z ? Xl1 : Xl0;
    const __nv_bfloat16* Yh = blockIdx.z ? Yh1 : Yh0;
    const __nv_bfloat16* Yl = blockIdx.z ? Yl1 : Yl0;
    __nv_bfloat16* Chi = blockIdx.z ? Chi1 : Chi0;
    __nv_bfloat16* Clo = blockIdx.z ? Clo1 : Clo0;
    float* Cf = blockIdx.z ? Cf1 : Cf0;
    int slot = blockIdx.z ? slot1 : slot0;

    int b = blockIdx.y;
    size_t base = (size_t)b << 16;
    Xh += base; Xl += base; Yh += base; Yl += base;
    int tileM = (blockIdx.x >> 1) << 7;
    int tileN = (blockIdx.x & 1) << 7;

    extern __shared__ __align__(128) char sm[];
    uint32_t smb = smem_u32(sm);

    int t = threadIdx.x;
    int w = t >> 5, wm = w & 1, wn = w >> 1;

    int xr = t >> 1, xq = t & 1;   // X: 128 rows x 2x32B
    int yr = t >> 4, yq = t & 15;  // Y: 32 rows x 16x16B

    wmma::fragment<wmma::accumulator, 16, 16, 16, float> acc[4][2];
    #pragma unroll
    for (int i = 0; i < 4; i++)
        #pragma unroll
        for (int j = 0; j < 2; j++) wmma::fill_fragment(acc[i][j], 0.0f);

    auto issue = [&](int kc, int s) {
        int k0 = kc << 5;
        uint32_t sb = smb + s * STAGE_B;
        {
            const __nv_bfloat16* gh = Xh + (size_t)(tileM + xr) * NN + k0 + xq * 16;
            const __nv_bfloat16* gl = Xl + (size_t)(tileM + xr) * NN + k0 + xq * 16;
            uint32_t d = sb + xr * (XLD * 2) + xq * 32;
            cpa16(d, gh);               cpa16(d + 16, gh + 8);
            cpa16(d + OFF_XL, gl);      cpa16(d + OFF_XL + 16, gl + 8);
        }
        {
            const __nv_bfloat16* gh = Yh + (size_t)(k0 + yr) * NN + tileN + yq * 8;
            const __nv_bfloat16* gl = Yl + (size_t)(k0 + yr) * NN + tileN + yq * 8;
            uint32_t d = sb + OFF_YH + yr * (YLD * 2) + yq * 16;
            cpa16(d, gh);               cpa16(d + 16 * (YLD * 2), gh + 16 * NN);
            cpa16(d + YARR_B, gl);      cpa16(d + YARR_B + 16 * (YLD * 2), gl + 16 * NN);
        }
        cpa_commit();
    };

    issue(0, 0);
    issue(1, 1);

    int scur = 0, sis = 2;
    #pragma unroll 1
    for (int kc = 0; kc < 8; kc++) {
        if (kc < 6) asm volatile("cp.async.wait_group 1;" ::: "memory");
        else        asm volatile("cp.async.wait_group 0;" ::: "memory");
        __syncthreads();
        if (kc < 6) issue(kc + 2, sis);

        const char* sb = sm + scur * STAGE_B;
        const __nv_bfloat16* bXh = (const __nv_bfloat16*)(sb);
        const __nv_bfloat16* bXl = (const __nv_bfloat16*)(sb + OFF_XL);
        const __nv_bfloat16* bYh = (const __nv_bfloat16*)(sb + OFF_YH);
        const __nv_bfloat16* bYl = (const __nv_bfloat16*)(sb + OFF_YL);

        #pragma unroll
        for (int kk = 0; kk < 2; kk++) {
            int ks = kk * 16;
            wmma::fragment<wmma::matrix_a, 16, 16, 16, __nv_bfloat16, wmma::row_major> ah[4], al[4];
            wmma::fragment<wmma::matrix_b, 16, 16, 16, __nv_bfloat16, wmma::row_major> bh[2], bl[2];
            #pragma unroll
            for (int i = 0; i < 4; i++) {
                wmma::load_matrix_sync(ah[i], bXh + (wm * 64 + i * 16) * XLD + ks, XLD);
                wmma::load_matrix_sync(al[i], bXl + (wm * 64 + i * 16) * XLD + ks, XLD);
            }
            #pragma unroll
            for (int j = 0; j < 2; j++) {
                wmma::load_matrix_sync(bh[j], bYh + ks * YLD + wn * 32 + j * 16, YLD);
                wmma::load_matrix_sync(bl[j], bYl + ks * YLD + wn * 32 + j * 16, YLD);
            }
            #pragma unroll
            for (int i = 0; i < 4; i++)
                #pragma unroll
                for (int j = 0; j < 2; j++) {
                    wmma::mma_sync(acc[i][j], ah[i], bh[j], acc[i][j]);
                    wmma::mma_sync(acc[i][j], ah[i], bl[j], acc[i][j]);
                    wmma::mma_sync(acc[i][j], al[i], bh[j], acc[i][j]);
                }
        }
        scur = (scur == 2) ? 0 : scur + 1;
        sis  = (sis  == 2) ? 0 : sis + 1;
        __syncthreads();
    }

    // epilogue: stage 128x128 fp32 tile in smem + diag slot
    float* cs = (float*)sm;
    #pragma unroll
    for (int i = 0; i < 4; i++)
        #pragma unroll
        for (int j = 0; j < 2; j++)
            wmma::store_matrix_sync(cs + (wm * 64 + i * 16) * CLD + wn * 32 + j * 16,
                                    acc[i][j], CLD, wmma::mem_row_major);
    __syncthreads();

    if (tileM == tileN && t < 128)
        out[((size_t)(b << 8) + tileM + t) * 8 + slot] = cs[t * CLD + t];

    if (Chi) {
        // bf16 hi/lo split (P2 — future GEMM operand)
        Chi += base; Clo += base;
        #pragma unroll
        for (int it = 0; it < 8; it++) {
            int idx = t + it * 256;
            int r = idx >> 4;
            int c = (idx & 15) << 3;
            const float* sp = cs + r * CLD + c;
            float f[8];
            #pragma unroll
            for (int q = 0; q < 8; q++) f[q] = sp[q];
            uint32_t hp[4], lp[4];
            #pragma unroll
            for (int q = 0; q < 4; q++) {
                __nv_bfloat16 h0 = __float2bfloat16_rn(f[2*q]);
                __nv_bfloat16 h1 = __float2bfloat16_rn(f[2*q+1]);
                __nv_bfloat162 hh; hh.x = h0; hh.y = h1;
                hp[q] = *(uint32_t*)&hh;
                __nv_bfloat162 ll;
                ll.x = __float2bfloat16_rn(f[2*q]   - bf2f(h0));
                ll.y = __float2bfloat16_rn(f[2*q+1] - bf2f(h1));
                lp[q] = *(uint32_t*)&ll;
            }
            *(uint4*)(Chi + (size_t)(tileM + r) * NN + tileN + c) = make_uint4(hp[0], hp[1], hp[2], hp[3]);
            *(uint4*)(Clo + (size_t)(tileM + r) * NN + tileN + c) = make_uint4(lp[0], lp[1], lp[2], lp[3]);
        }
    } else {
        // plain fp32 (P3/P4 — consumed only by diag3)
        Cf += base;
        #pragma unroll
        for (int it = 0; it < 8; it++) {
            int idx = t + it * 256;
            int r = idx >> 4;
            int c = (idx & 15) << 3;
            const float* sp = cs + r * CLD + c;
            float4 v0 = *(const float4*)(sp);
            float4 v1 = *(const float4*)(sp + 4);
            float* cp = Cf + (size_t)(tileM + r) * NN + tileN + c;
            *(float4*)cp = v0;
            *(float4*)(cp + 4) = v1;
        }
    }
}

// ---------------------------------------------------------------------------
// diag3 (R16 structure, fp32 P3/P4): all three dots share ONE staged
// P3-column tile (powers commute: d7 = diag(P4*P3) = <P4[i,:], P3[:,i]>).
//   d5 = <P2[i,:], P3[:,i]>,  d6 = <P3[i,:], P3[:,i]>,  d7 = <P4[i,:], P3[:,i]>
// P2 rows reconstructed from bf16 hi/lo; P3/P4 rows + c3 tile plain fp32.
// ---------------------------------------------------------------------------
__global__ void __launch_bounds__(256) diag3_kernel(const __nv_bfloat16* __restrict__ P2h,
                                                    const __nv_bfloat16* __restrict__ P2l,
                                                    const float* __restrict__ P3,
                                                    const float* __restrict__ P4,
                                                    float* __restrict__ out)
{
    __shared__ float c3[32][33];
    int b = blockIdx.x >> 3;
    int i0 = (blockIdx.x & 7) << 5;
    size_t base = (size_t)b << 16;
    int t = threadIdx.x;
    int il = t >> 3, jq = t & 7;
    int lc = t & 31, lr = t >> 5;

    const __nv_bfloat16* r2h = P2h + base + (size_t)(i0 + il) * NN;
    const __nv_bfloat16* r2l = P2l + base + (size_t)(i0 + il) * NN;
    const float* r3 = P3 + base + (size_t)(i0 + il) * NN;
    const float* r4 = P4 + base + (size_t)(i0 + il) * NN;

    float a5 = 0.f, a6 = 0.f, a7 = 0.f;
    #pragma unroll 1
    for (int jt = 0; jt < 8; jt++) {
        int j0 = jt << 5;
        #pragma unroll
        for (int qq = 0; qq < 4; qq++) {
            int jl = lr + qq * 8;
            c3[jl][lc] = P3[base + (size_t)(j0 + jl) * NN + i0 + lc];
        }
        __syncthreads();

        uint2 u2h = *(const uint2*)(r2h + j0 + jq * 4);
        uint2 u2l = *(const uint2*)(r2l + j0 + jq * 4);
        float4 x3 = *(const float4*)(r3 + j0 + jq * 4);
        float4 x4 = *(const float4*)(r4 + j0 + jq * 4);
        float x2[4];
        {
            __nv_bfloat162 h0 = *(__nv_bfloat162*)&u2h.x, h1 = *(__nv_bfloat162*)&u2h.y;
            __nv_bfloat162 l0 = *(__nv_bfloat162*)&u2l.x, l1 = *(__nv_bfloat162*)&u2l.y;
            x2[0] = bf2f(h0.x) + bf2f(l0.x); x2[1] = bf2f(h0.y) + bf2f(l0.y);
            x2[2] = bf2f(h1.x) + bf2f(l1.x); x2[3] = bf2f(h1.y) + bf2f(l1.y);
        }
        float x3a[4] = {x3.x, x3.y, x3.z, x3.w};
        float x4a[4] = {x4.x, x4.y, x4.z, x4.w};
        int jb = jq * 4;
        #pragma unroll
        for (int k = 0; k < 4; k++) {
            float cc3 = c3[jb + k][il];
            a5 = fmaf(x2[k],  cc3, a5);
            a6 = fmaf(x3a[k], cc3, a6);
            a7 = fmaf(x4a[k], cc3, a7);
        }
        __syncthreads();
    }
    #pragma unroll
    for (int o = 4; o; o >>= 1) {
        a5 += __shfl_down_sync(0xffffffffu, a5, o);
        a6 += __shfl_down_sync(0xffffffffu, a6, o);
        a7 += __shfl_down_sync(0xffffffffu, a7, o);
    }
    if (jq == 0) {
        size_t o = ((size_t)(b << 8) + i0 + il) * 8;
        out[o + 5] = a5;
        out[o + 6] = a6;
        out[o + 7] = a7;
    }
}

// ---------------------------------------------------------------------------
extern "C" void kernel_launch(void* const* d_in, const int* in_sizes, int n_in,
                              void* d_out, int out_size)
{
    const float* A = (const float*)d_in[0];
    float* out = (float*)d_out;

    __nv_bfloat16 *Phi, *Plo, *P2hi, *P2lo;
    float *P3, *P4;
    cudaGetSymbolAddress((void**)&Phi,  g_Phi);
    cudaGetSymbolAddress((void**)&Plo,  g_Plo);
    cudaGetSymbolAddress((void**)&P2hi, g_P2hi);
    cudaGetSymbolAddress((void**)&P2lo, g_P2lo);
    cudaGetSymbolAddress((void**)&P3,   g_P3);
    cudaGetSymbolAddress((void**)&P4,   g_P4);

    cudaFuncSetAttribute(gemm_wmma, cudaFuncAttributeMaxDynamicSharedMemorySize, GEMM_SMEM);

    // 1) P (bf16 hi/lo) + slots 0,1
    prep_kernel<<<8192, 256>>>(A, Phi, Plo, out);
    // 2) P2 = P * P (bf16 hi/lo split) + slot 2
    gemm_wmma<<<dim3(4, 256, 1), 256, GEMM_SMEM>>>(
        Phi, Plo, Phi, Plo, P2hi, P2lo, nullptr, 2,
        Phi, Plo, Phi, Plo, P2hi, P2lo, nullptr, 2, out);
    // 3) dual launch: P3 = P*P2 (fp32, slot 3) and P4 = P2*P2 (fp32, slot 4)
    gemm_wmma<<<dim3(4, 256, 2), 256, GEMM_SMEM>>>(
        Phi,  Plo,  P2hi, P2lo, nullptr, nullptr, P3, 3,
        P2hi, P2lo, P2hi, P2lo, nullptr, nullptr, P4, 4, out);
    // 4) slots 5,6,7
    diag3_kernel<<<2048, 256>>>(P2hi, P2lo, P3, P4, out);
}